// round 13
// baseline (speedup 1.0000x reference)
#include <cuda_runtime.h>
#include <cuda_bf16.h>
#include <cstdint>

// out[b,t,o] = (cummean_t x)[b,t,:] . W[t,:,o]
// B=4, T=1024, D=256, O=256. All fp32.
// Single fused kernel: 512 blocks x 128 threads, all co-resident (4/SM at
// 48KB smem). Order: scan x-loads first (critical path), then W cp.async
// prologue, then L2 prefetch of W chunks 4..15 so DRAM streams W under the
// whole scan phase. Grid barriers order scan -> cm reads; then the
// DRAM-bound GEMM mainloop.

#define BB 4
#define TT 1024
#define DD 256
#define OO 256

#define NSEG 128
#define SEGLEN 8

#define STAGES 5
#define DCHUNK 4                 // d-rows per stage
#define NCHUNK (DD / DCHUNK)     // 64

#define NBLK (TT / 2)            // 512 == BB * NSEG

__device__ float g_segsum[BB * NSEG * DD];      // 512 KB (L2-resident)
__device__ float g_cm[BB * TT * DD];            // 4 MB cumulative mean
__device__ unsigned g_bar_arr[2];               // zero-init; self-resetting
__device__ unsigned g_bar_dep[2];

__device__ __forceinline__ unsigned ld_acq(const unsigned* p) {
    unsigned v;
    asm volatile("ld.acquire.gpu.u32 %0, [%1];" : "=r"(v) : "l"(p));
    return v;
}

// grid barrier over n blocks; leader-only polling; self-resets for replay.
__device__ __forceinline__ void gbar(int i, unsigned n) {
    __syncthreads();
    if (threadIdx.x == 0) {
        __threadfence();
        atomicAdd(&g_bar_arr[i], 1u);
        while (ld_acq(&g_bar_arr[i]) < n) { __nanosleep(32); }
        unsigned d = atomicAdd(&g_bar_dep[i], 1u);
        if (d == n - 1u) {            // last departer: reset for next replay
            g_bar_arr[i] = 0u;
            __threadfence();
            g_bar_dep[i] = 0u;
        }
    }
    __syncthreads();
}

__device__ __forceinline__ void fma4(float4& acc, float s, const float4& v) {
    acc.x = fmaf(s, v.x, acc.x);
    acc.y = fmaf(s, v.y, acc.y);
    acc.z = fmaf(s, v.z, acc.z);
    acc.w = fmaf(s, v.w, acc.w);
}

__device__ __forceinline__ void add4(float4& a, const float4& v) {
    a.x += v.x; a.y += v.y; a.z += v.z; a.w += v.w;
}

__device__ __forceinline__ void cp16(void* smem_dst, const void* gmem_src) {
    uint32_t s = (uint32_t)__cvta_generic_to_shared(smem_dst);
    asm volatile("cp.async.cg.shared.global [%0], [%1], 16;\n"
                 :: "r"(s), "l"(gmem_src));
}

__device__ __forceinline__ void pfl2(const void* p) {
    asm volatile("prefetch.global.L2 [%0];" :: "l"(p));
}

__global__ __launch_bounds__(128) void k_fused(const float* __restrict__ x,
                                               const float* __restrict__ W,
                                               float* __restrict__ out) {
    __shared__ float4 ws[STAGES][2][DCHUNK][OO / 4];  // 40 KB
    __shared__ float4 cm_s[2][BB][DD / 4];            // 8 KB (aliased by scan)

    int tid = threadIdx.x;
    int t0 = blockIdx.x * 2;
    int tg = tid >> 6;        // 0..1
    int o4 = tid & 63;        // float4 O-column

    const float4* W4 = reinterpret_cast<const float4*>(W);

    auto issue = [&](int st, int ch) {
#pragma unroll
        for (int k = 0; k < 4; ++k) {
            int slot = tid + k * 128;          // 0..511
            int tg_ = slot >> 8;
            int dd  = (slot >> 6) & (DCHUNK - 1);
            int oo  = slot & 63;
            const float4* src = W4 + ((size_t)(t0 + tg_) * DD +
                                      (ch * DCHUNK + dd)) * (OO / 4) + oo;
            cp16(&ws[st][tg_][dd][oo], src);
        }
    };

    // ---- (1) scan x loads FIRST: they head the critical path ----
    int b = blockIdx.x >> 7;        // 0..3
    int s = blockIdx.x & 127;       // 0..127
    int d4 = tid & 63;
    int q  = tid >> 6;              // 0..1 (half-segment of 4 rows)
    int tbase = s * SEGLEN + q * 4;

    const float4* xp = reinterpret_cast<const float4*>(x) +
                       (size_t)(b * TT + tbase) * (DD / 4) + d4;
    float4 v[4];
#pragma unroll
    for (int i = 0; i < 4; ++i)
        v[i] = xp[(size_t)i * (DD / 4)];

    // ---- (2) W cp.async prologue (consumed only after gbar(1)) ----
#pragma unroll
    for (int p = 0; p < STAGES - 1; ++p) {
        issue(p, p);
        asm volatile("cp.async.commit_group;\n" ::: "memory");
    }

    // ---- (3) L2-prefetch W chunks 4..15 NOW: streams under the scan ----
    {
        const char* wrow0 = reinterpret_cast<const char*>(W) +
                            (size_t)t0 * DD * OO * 4;
#pragma unroll
        for (int tg_ = 0; tg_ < 2; ++tg_) {
            const char* base = wrow0 + (size_t)tg_ * DD * OO * 4;
#pragma unroll
            for (int it = 0; it < 3; ++it)
                pfl2(base + 16384 + (size_t)it * 16384 + tid * 128);
        }
    }

    // ---- (4) segment sum + publish ----
    {
        float4 (*qs)[64] = reinterpret_cast<float4(*)[64]>(&cm_s[0][0][0]);

        float4 hacc = v[0];
        add4(hacc, v[1]); add4(hacc, v[2]); add4(hacc, v[3]);
        qs[q][d4] = hacc;
        __syncthreads();

        if (q == 0) {
            float4 r = qs[0][d4];
            add4(r, qs[1][d4]);
            reinterpret_cast<float4*>(g_segsum)
                [(size_t)(b * NSEG + s) * (DD / 4) + d4] = r;
        }

        gbar(0, NBLK);   // all segment sums visible

        // ---- (5) prefix over prior segments, ILP-8 ----
        const float4* ss = reinterpret_cast<const float4*>(g_segsum) +
                           (size_t)b * NSEG * (DD / 4) + d4;
        float4 r0 = make_float4(0.f, 0.f, 0.f, 0.f);
        float4 r1 = r0, r2 = r0, r3 = r0, r4 = r0, r5 = r0, r6 = r0, r7 = r0;
        int sp = 0;
        for (; sp + 8 <= s; sp += 8) {
            float4 a0_ = ss[(size_t)(sp + 0) * (DD / 4)];
            float4 a1_ = ss[(size_t)(sp + 1) * (DD / 4)];
            float4 a2_ = ss[(size_t)(sp + 2) * (DD / 4)];
            float4 a3_ = ss[(size_t)(sp + 3) * (DD / 4)];
            float4 a4_ = ss[(size_t)(sp + 4) * (DD / 4)];
            float4 a5_ = ss[(size_t)(sp + 5) * (DD / 4)];
            float4 a6_ = ss[(size_t)(sp + 6) * (DD / 4)];
            float4 a7_ = ss[(size_t)(sp + 7) * (DD / 4)];
            add4(r0, a0_); add4(r1, a1_); add4(r2, a2_); add4(r3, a3_);
            add4(r4, a4_); add4(r5, a5_); add4(r6, a6_); add4(r7, a7_);
        }
        for (; sp < s; ++sp)
            add4(r0, ss[(size_t)sp * (DD / 4)]);
        add4(r0, r1); add4(r2, r3); add4(r4, r5); add4(r6, r7);
        add4(r0, r2); add4(r4, r6); add4(r0, r4);
        float4 run = r0;
        if (q == 1)
            add4(run, qs[0][d4]);   // first half of this segment

        float4* cp = reinterpret_cast<float4*>(g_cm) +
                     (size_t)(b * TT + tbase) * (DD / 4) + d4;
#pragma unroll
        for (int i = 0; i < 4; ++i) {
            add4(run, v[i]);
            float inv = 1.0f / (float)(tbase + i + 1);
            float4 o;
            o.x = run.x * inv; o.y = run.y * inv;
            o.z = run.z * inv; o.w = run.w * inv;
            cp[(size_t)i * (DD / 4)] = o;
        }
    }

    gbar(1, NBLK);   // cm complete & visible to every block

    // ---- (6) load cm tile ----
    const float4* cm_g = reinterpret_cast<const float4*>(g_cm);
#pragma unroll
    for (int k = 0; k < 4; ++k) {
        int idx = tid + k * 128;
        int tg_ = idx >> 8;
        int bb_ = (idx >> 6) & 3;
        int d4_ = idx & 63;
        cm_s[tg_][bb_][d4_] = cm_g[(size_t)(bb_ * TT + t0 + tg_) * (DD / 4) + d4_];
    }

    // ---- (7) GEMM mainloop (DRAM-bound streamer) ----
    float4 a0 = make_float4(0.f, 0.f, 0.f, 0.f);
    float4 a1 = a0, a2 = a0, a3 = a0;

    int st = 0;
    for (int ch = 0; ch < NCHUNK; ++ch) {
        asm volatile("cp.async.wait_group %0;\n" :: "n"(STAGES - 2) : "memory");
        __syncthreads();

        float4 c0 = cm_s[tg][0][ch];
        float4 c1 = cm_s[tg][1][ch];
        float4 c2 = cm_s[tg][2][ch];
        float4 c3 = cm_s[tg][3][ch];

        {
            float4 w = ws[st][tg][0][o4];
            fma4(a0, c0.x, w); fma4(a1, c1.x, w); fma4(a2, c2.x, w); fma4(a3, c3.x, w);
        }
        {
            float4 w = ws[st][tg][1][o4];
            fma4(a0, c0.y, w); fma4(a1, c1.y, w); fma4(a2, c2.y, w); fma4(a3, c3.y, w);
        }
        {
            float4 w = ws[st][tg][2][o4];
            fma4(a0, c0.z, w); fma4(a1, c1.z, w); fma4(a2, c2.z, w); fma4(a3, c3.z, w);
        }
        {
            float4 w = ws[st][tg][3][o4];
            fma4(a0, c0.w, w); fma4(a1, c1.w, w); fma4(a2, c2.w, w); fma4(a3, c3.w, w);
        }

        int stn = st + STAGES - 1;
        if (stn >= STAGES) stn -= STAGES;
        int nxt = ch + STAGES - 1;
        if (nxt < NCHUNK)
            issue(stn, nxt);
        asm volatile("cp.async.commit_group;\n" ::: "memory");

        if (++st == STAGES) st = 0;
    }

    int t = t0 + tg;
    float4* op = reinterpret_cast<float4*>(out);
    __stcs(&op[(size_t)(0 * TT + t) * (OO / 4) + o4], a0);
    __stcs(&op[(size_t)(1 * TT + t) * (OO / 4) + o4], a1);
    __stcs(&op[(size_t)(2 * TT + t) * (OO / 4) + o4], a2);
    __stcs(&op[(size_t)(3 * TT + t) * (OO / 4) + o4], a3);
}

extern "C" void kernel_launch(void* const* d_in, const int* in_sizes, int n_in,
                              void* d_out, int out_size) {
    const float* x = (const float*)d_in[0];   // (B,T,D)
    const float* W = (const float*)d_in[1];   // (T,D,O)
    float* out = (float*)d_out;               // (B,T,O)

    k_fused<<<NBLK, 128>>>(x, W, out);
}

// round 14
// speedup vs baseline: 1.0783x; 1.0783x over previous
#include <cuda_runtime.h>
#include <cuda_bf16.h>
#include <cstdint>

// out[b,t,o] = (cummean_t x)[b,t,:] . W[t,:,o]
// B=4, T=1024, D=256, O=256. All fp32.
// Single fused kernel, 512 blocks x 128 threads, all co-resident.
// No g_cm: each block derives its own 8 cm vectors from a 2-level sum
// hierarchy (seg8 + seg64) after two cheap grid barriers; the long prefix
// work happens AFTER the last barrier, overlapped with W cp.async streaming.

#define BB 4
#define TT 1024
#define DD 256
#define OO 256

#define STAGES 5
#define DCHUNK 4                 // d-rows per stage
#define NCHUNK (DD / DCHUNK)     // 64
#define NBLK (TT / 2)            // 512

__device__ float g_seg8[BB * 128 * DD];   // 512 KB: 8-row sums
__device__ float g_seg64[BB * 16 * DD];   // 64 KB: 64-row sums
__device__ unsigned g_bar_arr[2];         // zero-init; self-resetting
__device__ unsigned g_bar_dep[2];

__device__ __forceinline__ unsigned ld_acq(const unsigned* p) {
    unsigned v;
    asm volatile("ld.acquire.gpu.u32 %0, [%1];" : "=r"(v) : "l"(p));
    return v;
}

// grid barrier over n blocks; leader-only polling; self-resets for replay.
__device__ __forceinline__ void gbar(int i, unsigned n) {
    __syncthreads();
    if (threadIdx.x == 0) {
        __threadfence();
        atomicAdd(&g_bar_arr[i], 1u);
        while (ld_acq(&g_bar_arr[i]) < n) { __nanosleep(32); }
        unsigned d = atomicAdd(&g_bar_dep[i], 1u);
        if (d == n - 1u) {            // last departer: reset for next replay
            g_bar_arr[i] = 0u;
            __threadfence();
            g_bar_dep[i] = 0u;
        }
    }
    __syncthreads();
}

__device__ __forceinline__ void fma4(float4& acc, float s, const float4& v) {
    acc.x = fmaf(s, v.x, acc.x);
    acc.y = fmaf(s, v.y, acc.y);
    acc.z = fmaf(s, v.z, acc.z);
    acc.w = fmaf(s, v.w, acc.w);
}

__device__ __forceinline__ void add4(float4& a, const float4& v) {
    a.x += v.x; a.y += v.y; a.z += v.z; a.w += v.w;
}

// ILP-4 batched sum of n float4s strided by `stride` float4s.
__device__ __forceinline__ float4 sum_strided(const float4* p, int n, int stride) {
    float4 a0 = make_float4(0.f, 0.f, 0.f, 0.f);
    float4 a1 = a0, a2 = a0, a3 = a0;
    int i = 0;
    for (; i + 4 <= n; i += 4) {
        float4 v0 = p[(size_t)(i + 0) * stride];
        float4 v1 = p[(size_t)(i + 1) * stride];
        float4 v2 = p[(size_t)(i + 2) * stride];
        float4 v3 = p[(size_t)(i + 3) * stride];
        add4(a0, v0); add4(a1, v1); add4(a2, v2); add4(a3, v3);
    }
    for (; i < n; ++i)
        add4(a0, p[(size_t)i * stride]);
    add4(a0, a1); add4(a2, a3); add4(a0, a2);
    return a0;
}

__device__ __forceinline__ void cp16(void* smem_dst, const void* gmem_src) {
    uint32_t s = (uint32_t)__cvta_generic_to_shared(smem_dst);
    asm volatile("cp.async.cg.shared.global [%0], [%1], 16;\n"
                 :: "r"(s), "l"(gmem_src));
}

__global__ __launch_bounds__(128) void k_fused(const float* __restrict__ x,
                                               const float* __restrict__ W,
                                               float* __restrict__ out) {
    __shared__ float4 ws[STAGES][2][DCHUNK][OO / 4];  // 40 KB
    __shared__ float4 cm_s[2][BB][DD / 4];            // 8 KB (aliased in A)

    int tid = threadIdx.x;
    int t0 = blockIdx.x * 2;
    int tg = tid >> 6;        // 0..1
    int o4 = tid & 63;        // float4 O-column

    const float4* W4 = reinterpret_cast<const float4*>(W);
    const float4* x4 = reinterpret_cast<const float4*>(x);

    auto issue = [&](int st, int ch) {
#pragma unroll
        for (int k = 0; k < 4; ++k) {
            int slot = tid + k * 128;          // 0..511
            int tg_ = slot >> 8;
            int dd  = (slot >> 6) & (DCHUNK - 1);
            int oo  = slot & 63;
            const float4* src = W4 + ((size_t)(t0 + tg_) * DD +
                                      (ch * DCHUNK + dd)) * (OO / 4) + oo;
            cp16(&ws[st][tg_][dd][oo], src);
        }
    };

    // ---- Phase A: seg8 for (bscan = bid>>7, s = bid&127). x loads first. --
    int bscan = blockIdx.x >> 7;    // 0..3
    int s = blockIdx.x & 127;       // 0..127
    int d4 = tid & 63;
    int q  = tid >> 6;              // half-segment (4 rows each)

    const float4* xp = x4 + (size_t)(bscan * TT + s * 8 + q * 4) * (DD / 4) + d4;
    float4 v0 = xp[0 * (DD / 4)];
    float4 v1 = xp[1 * (DD / 4)];
    float4 v2 = xp[2 * (DD / 4)];
    float4 v3 = xp[3 * (DD / 4)];

    // W cp.async prologue (drains through the scan phases)
#pragma unroll
    for (int p = 0; p < STAGES - 1; ++p) {
        issue(p, p);
        asm volatile("cp.async.commit_group;\n" ::: "memory");
    }

    {
        float4 (*qs)[64] = reinterpret_cast<float4(*)[64]>(&cm_s[0][0][0]);
        float4 h = v0;
        add4(h, v1); add4(h, v2); add4(h, v3);
        qs[q][d4] = h;
        __syncthreads();
        if (q == 0) {
            float4 r = qs[0][d4];
            add4(r, qs[1][d4]);
            reinterpret_cast<float4*>(g_seg8)
                [(size_t)(bscan * 128 + s) * (DD / 4) + d4] = r;
        }
    }

    gbar(0, NBLK);   // all seg8 visible

    // ---- Phase A2: blocks 0..31 fold seg8 -> seg64 (4096 jobs) ----
    if (blockIdx.x < 32) {
        int j = blockIdx.x * 128 + tid;       // 0..4095
        int b_ = j >> 10;                      // 0..3
        int k_ = (j >> 6) & 15;                // 0..15
        int dj = j & 63;
        const float4* S8 = reinterpret_cast<const float4*>(g_seg8) +
                           (size_t)(b_ * 128 + k_ * 8) * (DD / 4) + dj;
        float4 r = sum_strided(S8, 8, DD / 4);
        reinterpret_cast<float4*>(g_seg64)
            [(size_t)(b_ * 16 + k_) * (DD / 4) + dj] = r;
    }

    gbar(1, NBLK);   // seg64 visible; from here every block is independent

    // ---- Phase B: private cm for this block's 2 t-rows, 4 b's ----
    {
        int p = tid >> 6;                      // 0..1 -> handles b = 2p, 2p+1
        int s64 = t0 >> 6;                     // # full 64-row supersegments
        int k8e = t0 >> 3;                     // # full 8-row segments
        int nx  = (t0 & 7) + 1;                // x rows [8*k8e .. t0]
        float i0 = 1.0f / (float)(t0 + 1);
        float i1 = 1.0f / (float)(t0 + 2);

#pragma unroll
        for (int bi = 0; bi < 2; ++bi) {
            int b = 2 * p + bi;
            const float4* S64 = reinterpret_cast<const float4*>(g_seg64) +
                                (size_t)(b * 16) * (DD / 4) + d4;
            const float4* S8  = reinterpret_cast<const float4*>(g_seg8) +
                                (size_t)(b * 128 + 8 * s64) * (DD / 4) + d4;
            const float4* X   = x4 + (size_t)(b * TT + 8 * k8e) * (DD / 4) + d4;

            float4 acc = sum_strided(S64, s64, DD / 4);
            add4(acc, sum_strided(S8, k8e - 8 * s64, DD / 4));
            add4(acc, sum_strided(X, nx, DD / 4));      // inclusive to t0
            float4 r1 = acc;
            add4(r1, X[(size_t)nx * (DD / 4)]);         // + row t0+1

            float4 c0, c1;
            c0.x = acc.x * i0; c0.y = acc.y * i0; c0.z = acc.z * i0; c0.w = acc.w * i0;
            c1.x = r1.x * i1;  c1.y = r1.y * i1;  c1.z = r1.z * i1;  c1.w = r1.w * i1;
            cm_s[0][b][d4] = c0;
            cm_s[1][b][d4] = c1;
        }
    }
    __syncthreads();

    // ---- GEMM mainloop (DRAM-bound streamer; unchanged) ----
    float4 a0 = make_float4(0.f, 0.f, 0.f, 0.f);
    float4 a1 = a0, a2 = a0, a3 = a0;

    int st = 0;
    for (int ch = 0; ch < NCHUNK; ++ch) {
        asm volatile("cp.async.wait_group %0;\n" :: "n"(STAGES - 2) : "memory");
        __syncthreads();

        float4 c0 = cm_s[tg][0][ch];
        float4 c1 = cm_s[tg][1][ch];
        float4 c2 = cm_s[tg][2][ch];
        float4 c3 = cm_s[tg][3][ch];

        {
            float4 w = ws[st][tg][0][o4];
            fma4(a0, c0.x, w); fma4(a1, c1.x, w); fma4(a2, c2.x, w); fma4(a3, c3.x, w);
        }
        {
            float4 w = ws[st][tg][1][o4];
            fma4(a0, c0.y, w); fma4(a1, c1.y, w); fma4(a2, c2.y, w); fma4(a3, c3.y, w);
        }
        {
            float4 w = ws[st][tg][2][o4];
            fma4(a0, c0.z, w); fma4(a1, c1.z, w); fma4(a2, c2.z, w); fma4(a3, c3.z, w);
        }
        {
            float4 w = ws[st][tg][3][o4];
            fma4(a0, c0.w, w); fma4(a1, c1.w, w); fma4(a2, c2.w, w); fma4(a3, c3.w, w);
        }

        int stn = st + STAGES - 1;
        if (stn >= STAGES) stn -= STAGES;
        int nxt = ch + STAGES - 1;
        if (nxt < NCHUNK)
            issue(stn, nxt);
        asm volatile("cp.async.commit_group;\n" ::: "memory");

        if (++st == STAGES) st = 0;
    }

    int t = t0 + tg;
    float4* op = reinterpret_cast<float4*>(out);
    __stcs(&op[(size_t)(0 * TT + t) * (OO / 4) + o4], a0);
    __stcs(&op[(size_t)(1 * TT + t) * (OO / 4) + o4], a1);
    __stcs(&op[(size_t)(2 * TT + t) * (OO / 4) + o4], a2);
    __stcs(&op[(size_t)(3 * TT + t) * (OO / 4) + o4], a3);
}

extern "C" void kernel_launch(void* const* d_in, const int* in_sizes, int n_in,
                              void* d_out, int out_size) {
    const float* x = (const float*)d_in[0];   // (B,T,D)
    const float* W = (const float*)d_in[1];   // (T,D,O)
    float* out = (float*)d_out;               // (B,T,O)

    k_fused<<<NBLK, 128>>>(x, W, out);
}